// round 1
// baseline (speedup 1.0000x reference)
#include <cuda_runtime.h>
#include <math.h>

#define DD 128
#define HH_ 128
#define WW_ 32
#define DHW (128*128*32)   // 524288 = 2^19
#define HW  (128*32)       // 4096
#define BB 2
#define EPSB 1e-5f

// ---------------- scratch (device globals; no allocations allowed) ----------------
__device__ float g_occ[BB*DHW];          // occupancy (B,1,D,H,W)
__device__ float g_x1[BB*32*DHW];        // conv1 raw output (pre-BN)
__device__ float g_x2[(size_t)BB*64*DHW];// conv2 raw output
__device__ float g_x3[(size_t)BB*64*DHW];// conv3 raw output
__device__ float g_min[6];               // per (b,dim) min
__device__ float g_sum[3][64];
__device__ float g_sumsq[3][64];
__device__ float g_scale[3][64];
__device__ float g_shift[3][64];

// ---------------- zero occupancy + stats accumulators ----------------
__global__ void zero_kernel() {
    int t = blockIdx.x * blockDim.x + threadIdx.x;
    if (t < BB*DHW) g_occ[t] = 0.0f;
    if (t < 192) { g_sum[t/64][t%64] = 0.0f; g_sumsq[t/64][t%64] = 0.0f; }
}

// ---------------- per (b,dim) min over N points (NaN -> 0) ----------------
__global__ void min_kernel(const float* __restrict__ pc, int N) {
    __shared__ float s[256];
    int id = blockIdx.x;                 // 0..5 : b*3+dim
    const float* p = pc + (size_t)id * N;
    float m = 1e30f;
    for (int i = threadIdx.x; i < N; i += 256) {
        float v = p[i];
        if (v != v) v = 0.0f;
        m = fminf(m, v);
    }
    s[threadIdx.x] = m; __syncthreads();
    for (int k = 128; k > 0; k >>= 1) {
        if (threadIdx.x < k) s[threadIdx.x] = fminf(s[threadIdx.x], s[threadIdx.x + k]);
        __syncthreads();
    }
    if (threadIdx.x == 0) g_min[id] = s[0];
}

// ---------------- scatter points into occupancy grid ----------------
__global__ void scatter_kernel(const float* __restrict__ pc, int N) {
    int t = blockIdx.x * blockDim.x + threadIdx.x;
    if (t >= BB * N) return;
    int b = t / N, j = t - b * N;
    const float* p = pc + (size_t)b * 3 * N;
    float x = p[j];       if (x != x) x = 0.0f;
    float y = p[N + j];   if (y != y) y = 0.0f;
    float z = p[2*N + j]; if (z != z) z = 0.0f;
    int ix = (int)floorf((x - g_min[b*3+0]) * 16.0f);  // 1/0.0625 == 16 exactly
    int iy = (int)floorf((y - g_min[b*3+1]) * 16.0f);
    int iz = (int)floorf((z - g_min[b*3+2]) * 16.0f);
    ix = min(max(ix, 0), 127);
    iy = min(max(iy, 0), 127);
    iz = min(max(iz, 0), 31);
    g_occ[b*DHW + ix*HW + iy*WW_ + iz] = 1.0f;
}

// ---------------- conv1: 1 -> 32, 3x3x3 SAME, + bias ----------------
__global__ void conv1_kernel(const float* __restrict__ w1, const float* __restrict__ b1) {
    __shared__ float sIn[3][10][35];
    __shared__ float sW[27][32];
    __shared__ float sB[32];
    int d = blockIdx.x, h0 = blockIdx.y * 8, b = blockIdx.z;
    int tid = threadIdx.x;
    for (int i = tid; i < 32*27; i += 256) { int oc = i/27, tap = i%27; sW[tap][oc] = w1[i]; }
    if (tid < 32) sB[tid] = b1[tid];
    for (int i = tid; i < 3*10*34; i += 256) {
        int ww = i % 34; int r = i / 34; int hh = r % 10; int kd = r / 10;
        int gd = d + kd - 1, gh = h0 + hh - 1, gw = ww - 1;
        float v = 0.0f;
        if (gd >= 0 && gd < DD && gh >= 0 && gh < HH_ && gw >= 0 && gw < WW_)
            v = g_occ[b*DHW + gd*HW + gh*WW_ + gw];
        sIn[kd][hh][ww] = v;
    }
    __syncthreads();
    int tx = tid & 31, ty = tid >> 5;
    float acc[32];
    #pragma unroll
    for (int oc = 0; oc < 32; oc++) acc[oc] = sB[oc];
    #pragma unroll
    for (int kd = 0; kd < 3; kd++)
    #pragma unroll
    for (int kh = 0; kh < 3; kh++) {
        float a0 = sIn[kd][ty+kh][tx], a1 = sIn[kd][ty+kh][tx+1], a2 = sIn[kd][ty+kh][tx+2];
        int t0 = kd*9 + kh*3;
        #pragma unroll
        for (int oc = 0; oc < 32; oc++)
            acc[oc] = fmaf(a0, sW[t0][oc], fmaf(a1, sW[t0+1][oc], fmaf(a2, sW[t0+2][oc], acc[oc])));
    }
    float* o = g_x1 + ((size_t)(b*32)*DD + d)*HW + (h0+ty)*WW_ + tx;
    #pragma unroll
    for (int oc = 0; oc < 32; oc++) o[(size_t)oc * DHW] = acc[oc];
}

// ---------------- conv2/conv3: CIN -> 64, bn+relu of previous stage applied on load ----------------
template<int CIN>
__global__ __launch_bounds__(256) void conv_kernel(const float* __restrict__ wt,
                                                   const float* __restrict__ bias) {
    constexpr int CCH = 4;
    constexpr int STAGE = (CIN == 32) ? 0 : 1;
    const float* in  = (CIN == 32) ? g_x1 : g_x2;
    float*       out = (CIN == 32) ? g_x2 : g_x3;
    __shared__ float sIn[CCH][3][18][35];
    __shared__ float sW[CCH*27*16];
    int d  = blockIdx.x;
    int h0 = blockIdx.y * 16;
    int og = blockIdx.z & 3;
    int b  = blockIdx.z >> 2;
    int ocbase = og * 16;
    int tid = threadIdx.x;
    int tx = tid & 15, ty = tid >> 4;
    float acc0[16], acc1[16];
    #pragma unroll
    for (int i = 0; i < 16; i++) { float bi = bias[ocbase + i]; acc0[i] = bi; acc1[i] = bi; }

    #pragma unroll 1
    for (int c0 = 0; c0 < CIN; c0 += CCH) {
        // weights: layout [c][tap][oc] (broadcast reads)
        for (int i = tid; i < CCH*27*16; i += 256) {
            int oc = i & 15; int r = i >> 4; int tap = r % 27; int c = r / 27;
            sW[i] = wt[((ocbase + oc)*CIN + c0 + c)*27 + tap];
        }
        // input tile with halo; apply bn+relu of previous layer (zeros stay zero padding)
        for (int i = tid; i < CCH*3*18*34; i += 256) {
            int ww = i % 34; int r = i / 34; int hh = r % 18; r /= 18; int kd = r % 3; int c = r / 3;
            int gd = d + kd - 1, gh = h0 + hh - 1, gw = ww - 1;
            float v = 0.0f;
            if (gd >= 0 && gd < DD && gh >= 0 && gh < HH_ && gw >= 0 && gw < WW_) {
                int cc = c0 + c;
                v = in[((size_t)(b*CIN + cc)*DD + gd)*HW + gh*WW_ + gw];
                v = fmaxf(fmaf(v, g_scale[STAGE][cc], g_shift[STAGE][cc]), 0.0f);
            }
            sIn[c][kd][hh][ww] = v;
        }
        __syncthreads();
        #pragma unroll
        for (int c = 0; c < CCH; c++)
        #pragma unroll
        for (int kd = 0; kd < 3; kd++)
        #pragma unroll
        for (int kh = 0; kh < 3; kh++) {
            const float* row = &sIn[c][kd][ty + kh][2*tx];
            float a0 = row[0], a1 = row[1], a2 = row[2], a3 = row[3];
            const float* wrow = &sW[(c*27 + kd*9 + kh*3) * 16];
            #pragma unroll
            for (int oc = 0; oc < 16; oc++) {
                float w0 = wrow[oc], w1 = wrow[16 + oc], w2 = wrow[32 + oc];
                acc0[oc] = fmaf(a0, w0, fmaf(a1, w1, fmaf(a2, w2, acc0[oc])));
                acc1[oc] = fmaf(a1, w0, fmaf(a2, w1, fmaf(a3, w2, acc1[oc])));
            }
        }
        __syncthreads();
    }
    float* o = out + ((size_t)(b*64 + ocbase)*DD + d)*HW + (h0 + ty)*WW_ + 2*tx;
    #pragma unroll
    for (int oc = 0; oc < 16; oc++) { o[0] = acc0[oc]; o[1] = acc1[oc]; o += DHW; }
}

// ---------------- per-channel sum / sumsq over (B,D,H,W) ----------------
__global__ void stats_kernel(int sel, int C) {
    const float* x = (sel == 0) ? g_x1 : (sel == 1) ? g_x2 : g_x3;
    __shared__ float ss[256], sq[256];
    int c = blockIdx.x;
    int base = blockIdx.y * 16384;      // 2*DHW / 64 chunks
    float s = 0.0f, q = 0.0f;
    for (int k = threadIdx.x; k < 16384; k += 256) {
        int t = base + k;
        int bb = t >> 19; int i = t & (DHW - 1);
        float v = x[(((size_t)(bb*C + c)) << 19) + i];
        s += v; q += v * v;
    }
    ss[threadIdx.x] = s; sq[threadIdx.x] = q; __syncthreads();
    for (int k = 128; k > 0; k >>= 1) {
        if (threadIdx.x < k) { ss[threadIdx.x] += ss[threadIdx.x+k]; sq[threadIdx.x] += sq[threadIdx.x+k]; }
        __syncthreads();
    }
    if (threadIdx.x == 0) {
        atomicAdd(&g_sum[sel][c], ss[0]);
        atomicAdd(&g_sumsq[sel][c], sq[0]);
    }
}

// ---------------- BN stats -> scale/shift ----------------
__global__ void finalize_kernel(const float* __restrict__ gamma, const float* __restrict__ beta,
                                int C, int stage) {
    int c = threadIdx.x;
    if (c < C) {
        const float invM = 1.0f / 1048576.0f;   // B*D*H*W
        float mean = g_sum[stage][c] * invM;
        float var  = g_sumsq[stage][c] * invM - mean * mean;
        float sc = gamma[c] * rsqrtf(var + EPSB);
        g_scale[stage][c] = sc;
        g_shift[stage][c] = beta[c] - mean * sc;
    }
}

// ---------------- bn3 + relu + max over D ----------------
__global__ void bevmax_kernel(float* __restrict__ out) {
    int t = blockIdx.x * blockDim.x + threadIdx.x;   // 0..524287 = (B,64,H,W)
    int w = t & 31; int r = t >> 5; int h = r & 127; r >>= 7; int c = r & 63; int b = r >> 6;
    const float* p = g_x3 + ((size_t)(b*64 + c)*DD)*HW + h*WW_ + w;
    float sc = g_scale[2][c], sh = g_shift[2][c];
    float m = -1e30f;
    #pragma unroll 4
    for (int d = 0; d < DD; d++) m = fmaxf(m, fmaf(p[(size_t)d*HW], sc, sh));
    out[t] = fmaxf(m, 0.0f);   // relu commutes with max
}

// ---------------- launch ----------------
extern "C" void kernel_launch(void* const* d_in, const int* in_sizes, int n_in,
                              void* d_out, int out_size) {
    const float* pc  = (const float*)d_in[0];
    const float* w1  = (const float*)d_in[1];
    const float* b1  = (const float*)d_in[2];
    const float* g1  = (const float*)d_in[3];
    const float* be1 = (const float*)d_in[4];
    const float* w2  = (const float*)d_in[5];
    const float* b2  = (const float*)d_in[6];
    const float* g2  = (const float*)d_in[7];
    const float* be2 = (const float*)d_in[8];
    const float* w3  = (const float*)d_in[9];
    const float* b3  = (const float*)d_in[10];
    const float* g3  = (const float*)d_in[11];
    const float* be3 = (const float*)d_in[12];
    float* out = (float*)d_out;
    int N = in_sizes[0] / (BB * 3);

    zero_kernel<<<(BB*DHW + 255)/256, 256>>>();
    min_kernel<<<6, 256>>>(pc, N);
    scatter_kernel<<<(BB*N + 255)/256, 256>>>(pc, N);

    conv1_kernel<<<dim3(DD, HH_/8, BB), 256>>>(w1, b1);
    stats_kernel<<<dim3(32, 64), 256>>>(0, 32);
    finalize_kernel<<<1, 64>>>(g1, be1, 32, 0);

    conv_kernel<32><<<dim3(DD, HH_/16, BB*4), 256>>>(w2, b2);
    stats_kernel<<<dim3(64, 64), 256>>>(1, 64);
    finalize_kernel<<<1, 64>>>(g2, be2, 64, 1);

    conv_kernel<64><<<dim3(DD, HH_/16, BB*4), 256>>>(w3, b3);
    stats_kernel<<<dim3(64, 64), 256>>>(2, 64);
    finalize_kernel<<<1, 64>>>(g3, be3, 64, 2);

    bevmax_kernel<<<(out_size + 255)/256, 256>>>(out);
}

// round 4
// speedup vs baseline: 1.0003x; 1.0003x over previous
#include <cuda_runtime.h>
#include <math.h>

#define DD 128
#define HH_ 128
#define WW_ 32
#define DHW (128*128*32)   // 524288 = 2^19
#define HW  (128*32)       // 4096
#define BB 2
#define EPSB 1e-5f

// ---------------- scratch (device globals; no allocations allowed) ----------------
__device__ float g_occ[BB*DHW];          // occupancy (B,1,D,H,W)
__device__ float g_x1[BB*32*DHW];        // conv1 raw output (pre-BN)
__device__ float g_x2[(size_t)BB*64*DHW];// conv2 raw output
__device__ float g_x3[(size_t)BB*64*DHW];// conv3 raw output
__device__ float g_min[6];               // per (b,dim) min
__device__ float g_sum[3][64];
__device__ float g_sumsq[3][64];
__device__ float g_scale[3][64];
__device__ float g_shift[3][64];

// ---------------- zero occupancy + stats accumulators ----------------
__global__ void zero_kernel() {
    int t = blockIdx.x * blockDim.x + threadIdx.x;
    if (t < BB*DHW) g_occ[t] = 0.0f;
    if (t < 192) { g_sum[t/64][t%64] = 0.0f; g_sumsq[t/64][t%64] = 0.0f; }
}

// ---------------- per (b,dim) min over N points (NaN -> 0) ----------------
__global__ void min_kernel(const float* __restrict__ pc, int N) {
    __shared__ float s[256];
    int id = blockIdx.x;                 // 0..5 : b*3+dim
    const float* p = pc + (size_t)id * N;
    float m = 1e30f;
    for (int i = threadIdx.x; i < N; i += 256) {
        float v = p[i];
        if (v != v) v = 0.0f;
        m = fminf(m, v);
    }
    s[threadIdx.x] = m; __syncthreads();
    for (int k = 128; k > 0; k >>= 1) {
        if (threadIdx.x < k) s[threadIdx.x] = fminf(s[threadIdx.x], s[threadIdx.x + k]);
        __syncthreads();
    }
    if (threadIdx.x == 0) g_min[id] = s[0];
}

// ---------------- scatter points into occupancy grid ----------------
__global__ void scatter_kernel(const float* __restrict__ pc, int N) {
    int t = blockIdx.x * blockDim.x + threadIdx.x;
    if (t >= BB * N) return;
    int b = t / N, j = t - b * N;
    const float* p = pc + (size_t)b * 3 * N;
    float x = p[j];       if (x != x) x = 0.0f;
    float y = p[N + j];   if (y != y) y = 0.0f;
    float z = p[2*N + j]; if (z != z) z = 0.0f;
    int ix = (int)floorf((x - g_min[b*3+0]) * 16.0f);  // 1/0.0625 == 16 exactly
    int iy = (int)floorf((y - g_min[b*3+1]) * 16.0f);
    int iz = (int)floorf((z - g_min[b*3+2]) * 16.0f);
    ix = min(max(ix, 0), 127);
    iy = min(max(iy, 0), 127);
    iz = min(max(iz, 0), 31);
    g_occ[b*DHW + ix*HW + iy*WW_ + iz] = 1.0f;
}

// ---------------- conv1: 1 -> 32, 3x3x3 SAME, + bias ----------------
__global__ void conv1_kernel(const float* __restrict__ w1, const float* __restrict__ b1) {
    __shared__ float sIn[3][10][35];
    __shared__ float sW[27][32];
    __shared__ float sB[32];
    int d = blockIdx.x, h0 = blockIdx.y * 8, b = blockIdx.z;
    int tid = threadIdx.x;
    for (int i = tid; i < 32*27; i += 256) { int oc = i/27, tap = i%27; sW[tap][oc] = w1[i]; }
    if (tid < 32) sB[tid] = b1[tid];
    for (int i = tid; i < 3*10*34; i += 256) {
        int ww = i % 34; int r = i / 34; int hh = r % 10; int kd = r / 10;
        int gd = d + kd - 1, gh = h0 + hh - 1, gw = ww - 1;
        float v = 0.0f;
        if (gd >= 0 && gd < DD && gh >= 0 && gh < HH_ && gw >= 0 && gw < WW_)
            v = g_occ[b*DHW + gd*HW + gh*WW_ + gw];
        sIn[kd][hh][ww] = v;
    }
    __syncthreads();
    int tx = tid & 31, ty = tid >> 5;
    float acc[32];
    #pragma unroll
    for (int oc = 0; oc < 32; oc++) acc[oc] = sB[oc];
    #pragma unroll
    for (int kd = 0; kd < 3; kd++)
    #pragma unroll
    for (int kh = 0; kh < 3; kh++) {
        float a0 = sIn[kd][ty+kh][tx], a1 = sIn[kd][ty+kh][tx+1], a2 = sIn[kd][ty+kh][tx+2];
        int t0 = kd*9 + kh*3;
        #pragma unroll
        for (int oc = 0; oc < 32; oc++)
            acc[oc] = fmaf(a0, sW[t0][oc], fmaf(a1, sW[t0+1][oc], fmaf(a2, sW[t0+2][oc], acc[oc])));
    }
    float* o = g_x1 + ((size_t)(b*32)*DD + d)*HW + (h0+ty)*WW_ + tx;
    #pragma unroll
    for (int oc = 0; oc < 32; oc++) o[(size_t)oc * DHW] = acc[oc];
}

// ---------------- conv2/conv3: CIN -> 64, bn+relu of previous stage applied on load ----------------
template<int CIN>
__global__ __launch_bounds__(256) void conv_kernel(const float* __restrict__ wt,
                                                   const float* __restrict__ bias) {
    constexpr int CCH = 4;
    constexpr int STAGE = (CIN == 32) ? 0 : 1;
    const float* in  = (CIN == 32) ? g_x1 : g_x2;
    float*       out = (CIN == 32) ? g_x2 : g_x3;
    __shared__ float sIn[CCH][3][18][35];
    __shared__ float sW[CCH*27*16];
    int d  = blockIdx.x;
    int h0 = blockIdx.y * 16;
    int og = blockIdx.z & 3;
    int b  = blockIdx.z >> 2;
    int ocbase = og * 16;
    int tid = threadIdx.x;
    int tx = tid & 15, ty = tid >> 4;
    float acc0[16], acc1[16];
    #pragma unroll
    for (int i = 0; i < 16; i++) { float bi = bias[ocbase + i]; acc0[i] = bi; acc1[i] = bi; }

    #pragma unroll 1
    for (int c0 = 0; c0 < CIN; c0 += CCH) {
        // weights: layout [c][tap][oc] (broadcast reads)
        for (int i = tid; i < CCH*27*16; i += 256) {
            int oc = i & 15; int r = i >> 4; int tap = r % 27; int c = r / 27;
            sW[i] = wt[((ocbase + oc)*CIN + c0 + c)*27 + tap];
        }
        // input tile with halo; apply bn+relu of previous layer (zeros stay zero padding)
        for (int i = tid; i < CCH*3*18*34; i += 256) {
            int ww = i % 34; int r = i / 34; int hh = r % 18; r /= 18; int kd = r % 3; int c = r / 3;
            int gd = d + kd - 1, gh = h0 + hh - 1, gw = ww - 1;
            float v = 0.0f;
            if (gd >= 0 && gd < DD && gh >= 0 && gh < HH_ && gw >= 0 && gw < WW_) {
                int cc = c0 + c;
                v = in[((size_t)(b*CIN + cc)*DD + gd)*HW + gh*WW_ + gw];
                v = fmaxf(fmaf(v, g_scale[STAGE][cc], g_shift[STAGE][cc]), 0.0f);
            }
            sIn[c][kd][hh][ww] = v;
        }
        __syncthreads();
        #pragma unroll
        for (int c = 0; c < CCH; c++)
        #pragma unroll
        for (int kd = 0; kd < 3; kd++)
        #pragma unroll
        for (int kh = 0; kh < 3; kh++) {
            const float* row = &sIn[c][kd][ty + kh][2*tx];
            float a0 = row[0], a1 = row[1], a2 = row[2], a3 = row[3];
            const float* wrow = &sW[(c*27 + kd*9 + kh*3) * 16];
            #pragma unroll
            for (int oc = 0; oc < 16; oc++) {
                float w0 = wrow[oc], w1 = wrow[16 + oc], w2 = wrow[32 + oc];
                acc0[oc] = fmaf(a0, w0, fmaf(a1, w1, fmaf(a2, w2, acc0[oc])));
                acc1[oc] = fmaf(a1, w0, fmaf(a2, w1, fmaf(a3, w2, acc1[oc])));
            }
        }
        __syncthreads();
    }
    float* o = out + ((size_t)(b*64 + ocbase)*DD + d)*HW + (h0 + ty)*WW_ + 2*tx;
    #pragma unroll
    for (int oc = 0; oc < 16; oc++) { o[0] = acc0[oc]; o[1] = acc1[oc]; o += DHW; }
}

// ---------------- per-channel sum / sumsq over (B,D,H,W) ----------------
__global__ void stats_kernel(int sel, int C) {
    const float* x = (sel == 0) ? g_x1 : (sel == 1) ? g_x2 : g_x3;
    __shared__ float ss[256], sq[256];
    int c = blockIdx.x;
    int base = blockIdx.y * 16384;      // 2*DHW / 64 chunks
    float s = 0.0f, q = 0.0f;
    for (int k = threadIdx.x; k < 16384; k += 256) {
        int t = base + k;
        int bb = t >> 19; int i = t & (DHW - 1);
        float v = x[(((size_t)(bb*C + c)) << 19) + i];
        s += v; q += v * v;
    }
    ss[threadIdx.x] = s; sq[threadIdx.x] = q; __syncthreads();
    for (int k = 128; k > 0; k >>= 1) {
        if (threadIdx.x < k) { ss[threadIdx.x] += ss[threadIdx.x+k]; sq[threadIdx.x] += sq[threadIdx.x+k]; }
        __syncthreads();
    }
    if (threadIdx.x == 0) {
        atomicAdd(&g_sum[sel][c], ss[0]);
        atomicAdd(&g_sumsq[sel][c], sq[0]);
    }
}

// ---------------- BN stats -> scale/shift ----------------
__global__ void finalize_kernel(const float* __restrict__ gamma, const float* __restrict__ beta,
                                int C, int stage) {
    int c = threadIdx.x;
    if (c < C) {
        const float invM = 1.0f / 1048576.0f;   // B*D*H*W
        float mean = g_sum[stage][c] * invM;
        float var  = g_sumsq[stage][c] * invM - mean * mean;
        float sc = gamma[c] * rsqrtf(var + EPSB);
        g_scale[stage][c] = sc;
        g_shift[stage][c] = beta[c] - mean * sc;
    }
}

// ---------------- bn3 + relu + max over D ----------------
__global__ void bevmax_kernel(float* __restrict__ out) {
    int t = blockIdx.x * blockDim.x + threadIdx.x;   // 0..524287 = (B,64,H,W)
    int w = t & 31; int r = t >> 5; int h = r & 127; r >>= 7; int c = r & 63; int b = r >> 6;
    const float* p = g_x3 + ((size_t)(b*64 + c)*DD)*HW + h*WW_ + w;
    float sc = g_scale[2][c], sh = g_shift[2][c];
    float m = -1e30f;
    #pragma unroll 4
    for (int d = 0; d < DD; d++) m = fmaxf(m, fmaf(p[(size_t)d*HW], sc, sh));
    out[t] = fmaxf(m, 0.0f);   // relu commutes with max
}

// ---------------- launch ----------------
extern "C" void kernel_launch(void* const* d_in, const int* in_sizes, int n_in,
                              void* d_out, int out_size) {
    const float* pc  = (const float*)d_in[0];
    const float* w1  = (const float*)d_in[1];
    const float* b1  = (const float*)d_in[2];
    const float* g1  = (const float*)d_in[3];
    const float* be1 = (const float*)d_in[4];
    const float* w2  = (const float*)d_in[5];
    const float* b2  = (const float*)d_in[6];
    const float* g2  = (const float*)d_in[7];
    const float* be2 = (const float*)d_in[8];
    const float* w3  = (const float*)d_in[9];
    const float* b3  = (const float*)d_in[10];
    const float* g3  = (const float*)d_in[11];
    const float* be3 = (const float*)d_in[12];
    float* out = (float*)d_out;
    int N = in_sizes[0] / (BB * 3);

    zero_kernel<<<(BB*DHW + 255)/256, 256>>>();
    min_kernel<<<6, 256>>>(pc, N);
    scatter_kernel<<<(BB*N + 255)/256, 256>>>(pc, N);

    conv1_kernel<<<dim3(DD, HH_/8, BB), 256>>>(w1, b1);
    stats_kernel<<<dim3(32, 64), 256>>>(0, 32);
    finalize_kernel<<<1, 64>>>(g1, be1, 32, 0);

    conv_kernel<32><<<dim3(DD, HH_/16, BB*4), 256>>>(w2, b2);
    stats_kernel<<<dim3(64, 64), 256>>>(1, 64);
    finalize_kernel<<<1, 64>>>(g2, be2, 64, 1);

    conv_kernel<64><<<dim3(DD, HH_/16, BB*4), 256>>>(w3, b3);
    stats_kernel<<<dim3(64, 64), 256>>>(2, 64);
    finalize_kernel<<<1, 64>>>(g3, be3, 64, 2);

    bevmax_kernel<<<(out_size + 255)/256, 256>>>(out);
}

// round 5
// speedup vs baseline: 3.1681x; 3.1671x over previous
#include <cuda_runtime.h>
#include <cuda_bf16.h>
#include <math.h>

#define DD 128
#define HH_ 128
#define WW_ 32
#define DHW (128*128*32)   // 524288 = 2^19
#define HW  (128*32)       // 4096
#define BB 2
#define EPSB 1e-5f

// ---------------- scratch (device globals; no allocations allowed) ----------------
__device__ float g_occ[BB*DHW];          // occupancy (B,1,D,H,W)
__device__ float g_x1[BB*32*DHW];        // conv1 raw output (pre-BN)
__device__ float g_x2[(size_t)BB*64*DHW];// conv2 raw output
__device__ float g_x3[(size_t)BB*64*DHW];// conv3 raw output
__device__ float g_min[6];               // per (b,dim) min
__device__ float g_sum[3][64];
__device__ float g_sumsq[3][64];
__device__ float g_scale[3][64];
__device__ float g_shift[3][64];

// split-bf16 weights, fragment-friendly layout.
// conv2 region at offset 0 (27*64*16 u32), conv3 at offset 27648 (27*64*32 u32)
#define W2_SZ (27*64*16)
#define W3_SZ (27*64*32)
__device__ unsigned int g_whi[W2_SZ + W3_SZ];
__device__ unsigned int g_wlo[W2_SZ + W3_SZ];

// ---------------- zero occupancy + stats accumulators ----------------
__global__ void zero_kernel() {
    int t = blockIdx.x * blockDim.x + threadIdx.x;
    if (t < BB*DHW) g_occ[t] = 0.0f;
    if (t < 192) { g_sum[t/64][t%64] = 0.0f; g_sumsq[t/64][t%64] = 0.0f; }
}

// ---------------- per (b,dim) min over N points (NaN -> 0) ----------------
__global__ void min_kernel(const float* __restrict__ pc, int N) {
    __shared__ float s[256];
    int id = blockIdx.x;                 // 0..5 : b*3+dim
    const float* p = pc + (size_t)id * N;
    float m = 1e30f;
    for (int i = threadIdx.x; i < N; i += 256) {
        float v = p[i];
        if (v != v) v = 0.0f;
        m = fminf(m, v);
    }
    s[threadIdx.x] = m; __syncthreads();
    for (int k = 128; k > 0; k >>= 1) {
        if (threadIdx.x < k) s[threadIdx.x] = fminf(s[threadIdx.x], s[threadIdx.x + k]);
        __syncthreads();
    }
    if (threadIdx.x == 0) g_min[id] = s[0];
}

// ---------------- scatter points into occupancy grid ----------------
__global__ void scatter_kernel(const float* __restrict__ pc, int N) {
    int t = blockIdx.x * blockDim.x + threadIdx.x;
    if (t >= BB * N) return;
    int b = t / N, j = t - b * N;
    const float* p = pc + (size_t)b * 3 * N;
    float x = p[j];       if (x != x) x = 0.0f;
    float y = p[N + j];   if (y != y) y = 0.0f;
    float z = p[2*N + j]; if (z != z) z = 0.0f;
    int ix = (int)floorf((x - g_min[b*3+0]) * 16.0f);
    int iy = (int)floorf((y - g_min[b*3+1]) * 16.0f);
    int iz = (int)floorf((z - g_min[b*3+2]) * 16.0f);
    ix = min(max(ix, 0), 127);
    iy = min(max(iy, 0), 127);
    iz = min(max(iz, 0), 31);
    g_occ[b*DHW + ix*HW + iy*WW_ + iz] = 1.0f;
}

// ---------------- conv1: 1 -> 32, 3x3x3 SAME, + bias (fp32, tiny) ----------------
__global__ void conv1_kernel(const float* __restrict__ w1, const float* __restrict__ b1) {
    __shared__ float sIn[3][10][35];
    __shared__ float sW[27][32];
    __shared__ float sB[32];
    int d = blockIdx.x, h0 = blockIdx.y * 8, b = blockIdx.z;
    int tid = threadIdx.x;
    for (int i = tid; i < 32*27; i += 256) { int oc = i/27, tap = i%27; sW[tap][oc] = w1[i]; }
    if (tid < 32) sB[tid] = b1[tid];
    for (int i = tid; i < 3*10*34; i += 256) {
        int ww = i % 34; int r = i / 34; int hh = r % 10; int kd = r / 10;
        int gd = d + kd - 1, gh = h0 + hh - 1, gw = ww - 1;
        float v = 0.0f;
        if (gd >= 0 && gd < DD && gh >= 0 && gh < HH_ && gw >= 0 && gw < WW_)
            v = g_occ[b*DHW + gd*HW + gh*WW_ + gw];
        sIn[kd][hh][ww] = v;
    }
    __syncthreads();
    int tx = tid & 31, ty = tid >> 5;
    float acc[32];
    #pragma unroll
    for (int oc = 0; oc < 32; oc++) acc[oc] = sB[oc];
    #pragma unroll
    for (int kd = 0; kd < 3; kd++)
    #pragma unroll
    for (int kh = 0; kh < 3; kh++) {
        float a0 = sIn[kd][ty+kh][tx], a1 = sIn[kd][ty+kh][tx+1], a2 = sIn[kd][ty+kh][tx+2];
        int t0 = kd*9 + kh*3;
        #pragma unroll
        for (int oc = 0; oc < 32; oc++)
            acc[oc] = fmaf(a0, sW[t0][oc], fmaf(a1, sW[t0+1][oc], fmaf(a2, sW[t0+2][oc], acc[oc])));
    }
    float* o = g_x1 + ((size_t)(b*32)*DD + d)*HW + (h0+ty)*WW_ + tx;
    #pragma unroll
    for (int oc = 0; oc < 32; oc++) o[(size_t)oc * DHW] = acc[oc];
}

// ---------------- weight prep: fp32 -> split bf16, fragment layout ----------------
// Storage index: base + (tap*64 + oc)*CINP + slot
//   logical pair p (channels 2p,2p+1), chunk kc = p/8, ppl = p%8
//   slot = kc*8 + (ppl%4)*2 + ppl/4     (so LDG.64 at slot 2t gives pairs t and t+4)
__global__ void prep_kernel(const float* __restrict__ w, int CIN, int base) {
    int t = blockIdx.x * blockDim.x + threadIdx.x;
    int CINP = CIN >> 1;
    int total = 27 * 64 * CINP;
    if (t >= total) return;
    int p   = t % CINP;
    int oc  = (t / CINP) % 64;
    int tap = t / (CINP * 64);
    int kc = p >> 3, ppl = p & 7;
    int slot = kc*8 + (ppl & 3)*2 + (ppl >> 2);
    int c = 2 * p;
    float v0 = w[((size_t)oc*CIN + c)*27 + tap];
    float v1 = w[((size_t)oc*CIN + c + 1)*27 + tap];
    __nv_bfloat16 h0 = __float2bfloat16_rn(v0);
    __nv_bfloat16 h1 = __float2bfloat16_rn(v1);
    __nv_bfloat16 l0 = __float2bfloat16_rn(v0 - __bfloat162float(h0));
    __nv_bfloat16 l1 = __float2bfloat16_rn(v1 - __bfloat162float(h1));
    unsigned int idx = base + (tap*64 + oc)*CINP + slot;
    g_whi[idx] = (unsigned int)__bfloat16_as_ushort(h0) | ((unsigned int)__bfloat16_as_ushort(h1) << 16);
    g_wlo[idx] = (unsigned int)__bfloat16_as_ushort(l0) | ((unsigned int)__bfloat16_as_ushort(l1) << 16);
}

__device__ __forceinline__ void mma_bf16(float& c0, float& c1, float& c2, float& c3,
                                         unsigned int a0, unsigned int a1,
                                         unsigned int a2, unsigned int a3,
                                         unsigned int b0, unsigned int b1) {
    asm volatile("mma.sync.aligned.m16n8k16.row.col.f32.bf16.bf16.f32 "
                 "{%0,%1,%2,%3}, {%4,%5,%6,%7}, {%8,%9}, {%0,%1,%2,%3};"
                 : "+f"(c0), "+f"(c1), "+f"(c2), "+f"(c3)
                 : "r"(a0), "r"(a1), "r"(a2), "r"(a3), "r"(b0), "r"(b1));
}

// ---------------- conv2/conv3: split-bf16 tensor-core implicit GEMM ----------------
// GEMM: M = 64 oc, N = 128 spatial (4h x 32w at fixed d), K = CIN*27
// 8 warps = 2 oc-warps (M=32 each) x 4 h-warps (N=32 each)
template<int CIN>
__global__ __launch_bounds__(256) void conv_mma_kernel(const float* __restrict__ bias) {
    constexpr int STAGE = (CIN == 32) ? 0 : 1;
    constexpr int CINP  = CIN >> 1;
    constexpr int WBASE = (CIN == 32) ? 0 : W2_SZ;
    const float* in  = (CIN == 32) ? g_x1 : g_x2;
    float*       out = (CIN == 32) ? g_x2 : g_x3;

    // activation tile, split bf16, pair-packed: [kd][h(6)][cpair(8)][w(34)+pad->40]
    __shared__ unsigned int sHi[3][6][8][40];
    __shared__ unsigned int sLo[3][6][8][40];

    int d  = blockIdx.x;
    int h0 = blockIdx.y * 4;
    int b  = blockIdx.z;
    int tid  = threadIdx.x;
    int wid  = tid >> 5;
    int lane = tid & 31;
    int mw = wid & 1;        // oc warp (0/1)
    int hw = wid >> 1;       // h row within tile (0..3)
    int gQ = lane >> 2;      // groupID
    int tQ = lane & 3;       // threadID within quad

    float acc[2][4][4];
    #pragma unroll
    for (int mt = 0; mt < 2; mt++)
        #pragma unroll
        for (int nt = 0; nt < 4; nt++)
            #pragma unroll
            for (int k = 0; k < 4; k++) acc[mt][nt][k] = 0.0f;

    float sc_loc[2], sh_loc[2];  // unused placeholder removal guard (kept minimal)

    #pragma unroll 1
    for (int kc = 0; kc < CIN/16; kc++) {
        int c0 = kc * 16;
        // ---- fill smem: bn+relu of previous stage, split to hi/lo bf16 pairs ----
        for (int i = tid; i < 3*6*8*34; i += 256) {
            int ww = i % 34; int r = i / 34;
            int pp = r & 7;  r >>= 3;
            int hh = r % 6;  int kd = r / 6;
            int gd = d + kd - 1, gh = h0 + hh - 1, gw = ww - 1;
            unsigned int hi = 0, lo = 0;
            if (gd >= 0 && gd < DD && gh >= 0 && gh < HH_ && gw >= 0 && gw < WW_) {
                int ca = c0 + 2*pp, cb = ca + 1;
                size_t sp = (size_t)gd*HW + gh*WW_ + gw;
                float va = in[((size_t)(b*CIN + ca) << 19) + sp];
                float vb = in[((size_t)(b*CIN + cb) << 19) + sp];
                va = fmaxf(fmaf(va, g_scale[STAGE][ca], g_shift[STAGE][ca]), 0.0f);
                vb = fmaxf(fmaf(vb, g_scale[STAGE][cb], g_shift[STAGE][cb]), 0.0f);
                __nv_bfloat16 ha = __float2bfloat16_rn(va);
                __nv_bfloat16 hb = __float2bfloat16_rn(vb);
                __nv_bfloat16 la = __float2bfloat16_rn(va - __bfloat162float(ha));
                __nv_bfloat16 lb = __float2bfloat16_rn(vb - __bfloat162float(hb));
                hi = (unsigned int)__bfloat16_as_ushort(ha) | ((unsigned int)__bfloat16_as_ushort(hb) << 16);
                lo = (unsigned int)__bfloat16_as_ushort(la) | ((unsigned int)__bfloat16_as_ushort(lb) << 16);
            }
            sHi[kd][hh][pp][ww] = hi;
            sLo[kd][hh][pp][ww] = lo;
        }
        __syncthreads();

        // ---- compute: 27 taps, k=16 channels each ----
        #pragma unroll 1
        for (int kd = 0; kd < 3; kd++) {
            #pragma unroll 1
            for (int kh = 0; kh < 3; kh++) {
                const unsigned int* rowHi = &sHi[kd][hw + kh][0][0];
                const unsigned int* rowLo = &sLo[kd][hw + kh][0][0];
                #pragma unroll
                for (int kw = 0; kw < 3; kw++) {
                    int tap = (kd*3 + kh)*3 + kw;
                    // B fragments (activations) from smem
                    unsigned int bh0[4], bh1[4], bl0[4], bl1[4];
                    #pragma unroll
                    for (int nt = 0; nt < 4; nt++) {
                        int idx = tQ*40 + nt*8 + gQ + kw;
                        bh0[nt] = rowHi[idx];
                        bh1[nt] = rowHi[idx + 160];   // cpair + 4
                        bl0[nt] = rowLo[idx];
                        bl1[nt] = rowLo[idx + 160];
                    }
                    // A fragments (weights) from global, LDG.64
                    uint2 ah[2][2], al[2][2];
                    #pragma unroll
                    for (int mt = 0; mt < 2; mt++) {
                        int oc = mw*32 + mt*16 + gQ;
                        unsigned int widx = WBASE + (tap*64 + oc)*CINP + kc*8 + tQ*2;
                        ah[mt][0] = *(const uint2*)&g_whi[widx];
                        ah[mt][1] = *(const uint2*)&g_whi[widx + 8*CINP];
                        al[mt][0] = *(const uint2*)&g_wlo[widx];
                        al[mt][1] = *(const uint2*)&g_wlo[widx + 8*CINP];
                    }
                    #pragma unroll
                    for (int mt = 0; mt < 2; mt++) {
                        #pragma unroll
                        for (int nt = 0; nt < 4; nt++) {
                            float* A = acc[mt][nt];
                            mma_bf16(A[0], A[1], A[2], A[3],
                                     ah[mt][0].x, ah[mt][1].x, ah[mt][0].y, ah[mt][1].y,
                                     bh0[nt], bh1[nt]);
                            mma_bf16(A[0], A[1], A[2], A[3],
                                     ah[mt][0].x, ah[mt][1].x, ah[mt][0].y, ah[mt][1].y,
                                     bl0[nt], bl1[nt]);
                            mma_bf16(A[0], A[1], A[2], A[3],
                                     al[mt][0].x, al[mt][1].x, al[mt][0].y, al[mt][1].y,
                                     bh0[nt], bh1[nt]);
                        }
                    }
                }
            }
        }
        __syncthreads();
    }

    // ---- store with bias (raw pre-BN output) ----
    int h = h0 + hw;
    #pragma unroll
    for (int mt = 0; mt < 2; mt++) {
        int ocA = mw*32 + mt*16 + gQ;
        int ocB = ocA + 8;
        float bA = bias[ocA], bC = bias[ocB];
        float* oA = out + ((size_t)(b*64 + ocA)*DD + d)*HW + h*WW_;
        float* oB = out + ((size_t)(b*64 + ocB)*DD + d)*HW + h*WW_;
        #pragma unroll
        for (int nt = 0; nt < 4; nt++) {
            int w = nt*8 + tQ*2;
            float2 vA = make_float2(acc[mt][nt][0] + bA, acc[mt][nt][1] + bA);
            float2 vB = make_float2(acc[mt][nt][2] + bC, acc[mt][nt][3] + bC);
            *(float2*)&oA[w] = vA;
            *(float2*)&oB[w] = vB;
        }
    }
    (void)sc_loc; (void)sh_loc;
}

// ---------------- per-channel sum / sumsq over (B,D,H,W) ----------------
__global__ void stats_kernel(int sel, int C) {
    const float* x = (sel == 0) ? g_x1 : (sel == 1) ? g_x2 : g_x3;
    __shared__ float ss[256], sq[256];
    int c = blockIdx.x;
    int base = blockIdx.y * 16384;
    float s = 0.0f, q = 0.0f;
    for (int k = threadIdx.x; k < 16384; k += 256) {
        int t = base + k;
        int bb = t >> 19; int i = t & (DHW - 1);
        float v = x[(((size_t)(bb*C + c)) << 19) + i];
        s += v; q += v * v;
    }
    ss[threadIdx.x] = s; sq[threadIdx.x] = q; __syncthreads();
    for (int k = 128; k > 0; k >>= 1) {
        if (threadIdx.x < k) { ss[threadIdx.x] += ss[threadIdx.x+k]; sq[threadIdx.x] += sq[threadIdx.x+k]; }
        __syncthreads();
    }
    if (threadIdx.x == 0) {
        atomicAdd(&g_sum[sel][c], ss[0]);
        atomicAdd(&g_sumsq[sel][c], sq[0]);
    }
}

// ---------------- BN stats -> scale/shift ----------------
__global__ void finalize_kernel(const float* __restrict__ gamma, const float* __restrict__ beta,
                                int C, int stage) {
    int c = threadIdx.x;
    if (c < C) {
        const float invM = 1.0f / 1048576.0f;
        float mean = g_sum[stage][c] * invM;
        float var  = g_sumsq[stage][c] * invM - mean * mean;
        float sc = gamma[c] * rsqrtf(var + EPSB);
        g_scale[stage][c] = sc;
        g_shift[stage][c] = beta[c] - mean * sc;
    }
}

// ---------------- bn3 + relu + max over D ----------------
__global__ void bevmax_kernel(float* __restrict__ out) {
    int t = blockIdx.x * blockDim.x + threadIdx.x;
    int w = t & 31; int r = t >> 5; int h = r & 127; r >>= 7; int c = r & 63; int b = r >> 6;
    const float* p = g_x3 + ((size_t)(b*64 + c)*DD)*HW + h*WW_ + w;
    float sc = g_scale[2][c], sh = g_shift[2][c];
    float m = -1e30f;
    #pragma unroll 4
    for (int d = 0; d < DD; d++) m = fmaxf(m, fmaf(p[(size_t)d*HW], sc, sh));
    out[t] = fmaxf(m, 0.0f);
}

// ---------------- launch ----------------
extern "C" void kernel_launch(void* const* d_in, const int* in_sizes, int n_in,
                              void* d_out, int out_size) {
    const float* pc  = (const float*)d_in[0];
    const float* w1  = (const float*)d_in[1];
    const float* b1  = (const float*)d_in[2];
    const float* g1  = (const float*)d_in[3];
    const float* be1 = (const float*)d_in[4];
    const float* w2  = (const float*)d_in[5];
    const float* b2  = (const float*)d_in[6];
    const float* g2  = (const float*)d_in[7];
    const float* be2 = (const float*)d_in[8];
    const float* w3  = (const float*)d_in[9];
    const float* b3  = (const float*)d_in[10];
    const float* g3  = (const float*)d_in[11];
    const float* be3 = (const float*)d_in[12];
    float* out = (float*)d_out;
    int N = in_sizes[0] / (BB * 3);

    zero_kernel<<<(BB*DHW + 255)/256, 256>>>();
    min_kernel<<<6, 256>>>(pc, N);
    scatter_kernel<<<(BB*N + 255)/256, 256>>>(pc, N);

    // weight prep (split bf16 fragment layout)
    prep_kernel<<<(27*64*16 + 255)/256, 256>>>(w2, 32, 0);
    prep_kernel<<<(27*64*32 + 255)/256, 256>>>(w3, 64, W2_SZ);

    conv1_kernel<<<dim3(DD, HH_/8, BB), 256>>>(w1, b1);
    stats_kernel<<<dim3(32, 64), 256>>>(0, 32);
    finalize_kernel<<<1, 64>>>(g1, be1, 32, 0);

    conv_mma_kernel<32><<<dim3(DD, HH_/4, BB), 256>>>(b2);
    stats_kernel<<<dim3(64, 64), 256>>>(1, 64);
    finalize_kernel<<<1, 64>>>(g2, be2, 64, 1);

    conv_mma_kernel<64><<<dim3(DD, HH_/4, BB), 256>>>(b3);
    stats_kernel<<<dim3(64, 64), 256>>>(2, 64);
    finalize_kernel<<<1, 64>>>(g3, be3, 64, 2);

    bevmax_kernel<<<(out_size + 255)/256, 256>>>(out);
}